// round 11
// baseline (speedup 1.0000x reference)
#include <cuda_runtime.h>
#include <cuda_fp16.h>
#include <math.h>
#include <stdint.h>

#define B_   4
#define NB   8          // flattened images
#define NC   256        // codes
#define CD   256        // channels
#define H_   96
#define W_   192
#define HW   (H_*W_)    // 18432
#define NTILE 144       // HW/128

// ---------------- global scratch (.bss) ----------------
__device__ __align__(256) __half g_Wt[(size_t)NB * HW * NC];    // sigmoid weights [b][p][n] fp16
__device__ __align__(256) __half g_WsTh[(size_t)NB * HW * NC];  // centered softmax weights, tile-swizzled fp16
__device__ __align__(256) __half g_B1h[NC * CD];                // cb[n][c]/norm2[n], tiled
__device__ __align__(256) __half g_B2h[NC * CD];                // cb as rows c, k=n, tiled
__device__ float g_colsum[CD];                                  // (1/256)*sum_n cb[n][c]
__device__ float g_norm[NC];
__device__ int   g_masked[NC];
__device__ float g_theta[NB][6];

// ---------------- helpers ----------------
__device__ __forceinline__ uint32_t smem_u32(const void* p) {
    uint32_t a;
    asm("{ .reg .u64 t; cvta.to.shared.u64 t, %1; cvt.u32.u64 %0, t; }" : "=r"(a) : "l"(p));
    return a;
}

// SW128 swizzle: byte offset within a 128-row x 128-byte tile
__device__ __forceinline__ int swz(int row, int bytecol) {
    return row * 128 + (bytecol ^ ((row & 7) << 4));
}

#define LDSM4(d0, d1, d2, d3, a) \
    asm volatile("ldmatrix.sync.aligned.m8n8.x4.shared.b16 {%0,%1,%2,%3}, [%4];" \
                 : "=r"(d0), "=r"(d1), "=r"(d2), "=r"(d3) : "r"(a))

// fp16-accumulate (both GEMMs — full-rate HMMA on sm_103a)
#define MMA16816H(d, a0, a1, a2, a3, b0, b1) \
    asm volatile("mma.sync.aligned.m16n8k16.row.col.f16.f16.f16.f16 " \
                 "{%0,%1}, {%2,%3,%4,%5}, {%6,%7}, {%0,%1};" \
                 : "+r"((d)[0]), "+r"((d)[1]) \
                 : "r"(a0), "r"(a1), "r"(a2), "r"(a3), "r"(b0), "r"(b1))

#define CP16(dst, src) \
    asm volatile("cp.async.cg.shared.global [%0], [%1], 16;" :: "r"(dst), "l"(src))
#define CP_COMMIT() asm volatile("cp.async.commit_group;" ::: "memory")
#define CP_WAIT(n)  asm volatile("cp.async.wait_group %0;" :: "n"(n) : "memory")

// ---------------------------------------------------------------------------
// Setup: per-code norm^2, cosine mask, theta copy. Warp-coalesced pub scan.
// ---------------------------------------------------------------------------
__global__ __launch_bounds__(256) void setup_kernel(const float* __restrict__ cb,
                                                    const float* __restrict__ pub,
                                                    const float* __restrict__ aff) {
    __shared__ float cbrow[256];
    __shared__ float sqs[8];
    __shared__ float wmaxs[8];
    const int n = blockIdx.x, t = threadIdx.x;
    const int w = t >> 5, l = t & 31;

    float v = cb[n * CD + t];
    cbrow[t] = v;
    float sq = v * v;
#pragma unroll
    for (int o = 16; o > 0; o >>= 1) sq += __shfl_xor_sync(0xffffffffu, sq, o);
    if (l == 0) sqs[w] = sq;
    __syncthreads();
    float cbn2 = 0.f;
#pragma unroll
    for (int i = 0; i < 8; i++) cbn2 += sqs[i];

    float wmax = -1e30f;
    for (int i = 0; i < 32; i++) {
        const int r = w * 32 + i;
        const float* pr = pub + r * CD + l * 8;
        const float* cr = cbrow + l * 8;
        float dot = 0.f, pn2 = 0.f;
#pragma unroll
        for (int j = 0; j < 2; j++) {
            float4 p4 = *(const float4*)(pr + j * 4);
            float4 c4 = *(const float4*)(cr + j * 4);
            dot += p4.x * c4.x + p4.y * c4.y + p4.z * c4.z + p4.w * c4.w;
            pn2 += p4.x * p4.x + p4.y * p4.y + p4.z * p4.z + p4.w * p4.w;
        }
#pragma unroll
        for (int o = 16; o > 0; o >>= 1) {
            dot += __shfl_xor_sync(0xffffffffu, dot, o);
            pn2 += __shfl_xor_sync(0xffffffffu, pn2, o);
        }
        wmax = fmaxf(wmax, dot * rsqrtf(cbn2 * pn2));
    }
    if (l == 0) wmaxs[w] = wmax;
    __syncthreads();
    if (t == 0) {
        float m = wmaxs[0];
#pragma unroll
        for (int i = 1; i < 8; i++) m = fmaxf(m, wmaxs[i]);
        g_masked[n] = (m <= 0.5f) ? 1 : 0;
        g_norm[n]   = cbn2;
    }
    if (n == 0 && t < NB * 6) g_theta[t / 6][t % 6] = aff[(t / 6) * 12 + (t % 6)];
}

// ---------------------------------------------------------------------------
// Prep: fp16 pre-swizzled operands + column-sum for the mean term.
// ---------------------------------------------------------------------------
__global__ __launch_bounds__(256) void prep_kernel(const float* __restrict__ cb) {
    const int r = blockIdx.x, t = threadIdx.x;
    const float inv = 1.f / g_norm[r];

    {   // B1: row n=r, k=c=t
        float x = cb[r * CD + t] * inv;
        int e = (r >> 7) * 32768 + (t >> 6) * 8192 + (swz(r & 127, 2 * (t & 63)) >> 1);
        g_B1h[e] = __float2half(x);
    }
    {   // B2: row c=r, k=n=t
        float x = cb[t * CD + r];
        int e = (r >> 7) * 32768 + (t >> 6) * 8192 + (swz(r & 127, 2 * (t & 63)) >> 1);
        g_B2h[e] = __float2half(x);
    }
}

// colsum[c] = (1/256) * sum_n cb[n][c]
__global__ __launch_bounds__(256) void colsum_kernel(const float* __restrict__ cb) {
    const int c = threadIdx.x;
    float s = 0.f;
#pragma unroll 8
    for (int n = 0; n < NC; n++) s += cb[n * CD + c];
    g_colsum[c] = s * (1.0f / 256.0f);
}

// ---------------------------------------------------------------------------
// GEMM1: Wt[p][n] = sigmoid( sum_c feat[c][p] * cb[n][c] / norm2[n] )
// fp16 accumulators. CTA: 128p x 128n; grid (2, 144, 8); 2 CTAs/SM.
// ---------------------------------------------------------------------------
__global__ __launch_bounds__(256, 2) void gemm1_mma(const float* __restrict__ feat) {
    extern __shared__ char smem_raw[];
    uint32_t sb0 = smem_u32(smem_raw);
    uint32_t base = (sb0 + 127u) & ~127u;
    char* smem = smem_raw + (base - sb0);

    const int tid = threadIdx.x;
    const int lane = tid & 31, warp = tid >> 5;
    const int wm = warp >> 2;        // 0..1 -> m offset wm*64
    const int wn = warp & 3;         // 0..3 -> n offset wn*32
    const int b  = blockIdx.z;
    const int ny = blockIdx.x;       // n block 0/1 (fastest: L2 pairing)
    const int p0 = blockIdx.y * 128;

    // issue all B stage copies (4 groups)
    {
        const char* src = (const char*)(g_B1h + ny * 32768);
#pragma unroll
        for (int s = 0; s < 4; s++) {
#pragma unroll
            for (int k = 0; k < 4; k++) {
                int idx = tid + k * 256;
                CP16(base + s * 16384 + idx * 16, src + s * 16384 + idx * 16);
            }
            CP_COMMIT();
        }
    }

    // ldmatrix per-lane address precompute
    int rA_off[4], xmA[4];
#pragma unroll
    for (int mt = 0; mt < 4; mt++) {
        int r = wm * 64 + mt * 16 + (lane & 15);
        rA_off[mt] = r * 128;
        xmA[mt] = (r & 7) << 4;
    }
    const int cb0A = (lane >> 4) << 4;
    int rB_off[2], xmB[2];
#pragma unroll
    for (int g = 0; g < 2; g++) {
        int r = wn * 32 + g * 16 + ((lane >> 4) << 3) + (lane & 7);
        rB_off[g] = r * 128;
        xmB[g] = (r & 7) << 4;
    }
    const int cb0B = ((lane >> 3) & 1) << 4;

    uint32_t acc[4][4][2];
#pragma unroll
    for (int i = 0; i < 4; i++)
#pragma unroll
        for (int j = 0; j < 4; j++) { acc[i][j][0] = 0u; acc[i][j][1] = 0u; }

    const float* fbase = feat + (size_t)b * CD * HW + p0;
    float ar[32];

    // prologue: load + store stage 0 A
#pragma unroll
    for (int i = 0; i < 16; i++) {
        int idx = tid + i * 256;
        int cp = idx >> 7, p = idx & 127;
        ar[2 * i]     = fbase[(size_t)(2 * cp) * HW + p];
        ar[2 * i + 1] = fbase[(size_t)(2 * cp + 1) * HW + p];
    }
    {
        char* A0 = smem + 65536;
#pragma unroll
        for (int i = 0; i < 16; i++) {
            int idx = tid + i * 256;
            int cp = idx >> 7, p = idx & 127;
            *(__half2*)(A0 + swz(p, 4 * cp)) =
                __floats2half2_rn(ar[2 * i], ar[2 * i + 1]);
        }
    }

    for (int s = 0; s < 4; s++) {
        // prefetch next A stage into regs
        if (s < 3) {
            const float* fs = fbase + (size_t)(s + 1) * 64 * HW;
#pragma unroll
            for (int i = 0; i < 16; i++) {
                int idx = tid + i * 256;
                int cp = idx >> 7, p = idx & 127;
                ar[2 * i]     = fs[(size_t)(2 * cp) * HW + p];
                ar[2 * i + 1] = fs[(size_t)(2 * cp + 1) * HW + p];
            }
        }
        if (s == 0) CP_WAIT(3);
        else if (s == 1) CP_WAIT(2);
        else if (s == 2) CP_WAIT(1);
        else CP_WAIT(0);
        __syncthreads();

        const uint32_t Abuf = base + 65536 + (s & 1) * 16384;
        const uint32_t Bst  = base + s * 16384;
#pragma unroll
        for (int ks = 0; ks < 4; ks++) {
            uint32_t a[4][4], bf[4][2];
#pragma unroll
            for (int mt = 0; mt < 4; mt++)
                LDSM4(a[mt][0], a[mt][1], a[mt][2], a[mt][3],
                      Abuf + rA_off[mt] + ((ks * 32 + cb0A) ^ xmA[mt]));
#pragma unroll
            for (int g = 0; g < 2; g++) {
                uint32_t r0, r1, r2, r3;
                LDSM4(r0, r1, r2, r3, Bst + rB_off[g] + ((ks * 32 + cb0B) ^ xmB[g]));
                bf[2 * g][0] = r0; bf[2 * g][1] = r1;
                bf[2 * g + 1][0] = r2; bf[2 * g + 1][1] = r3;
            }
#pragma unroll
            for (int mt = 0; mt < 4; mt++)
#pragma unroll
                for (int nt = 0; nt < 4; nt++)
                    MMA16816H(acc[mt][nt], a[mt][0], a[mt][1], a[mt][2], a[mt][3],
                              bf[nt][0], bf[nt][1]);
        }

        if (s < 3) {
            char* An = smem + 65536 + ((s + 1) & 1) * 16384;
#pragma unroll
            for (int i = 0; i < 16; i++) {
                int idx = tid + i * 256;
                int cp = idx >> 7, p = idx & 127;
                *(__half2*)(An + swz(p, 4 * cp)) =
                    __floats2half2_rn(ar[2 * i], ar[2 * i + 1]);
            }
        }
        __syncthreads();
    }

    // epilogue: sigmoid + fp16 STG (rows p, contiguous n)
    __half* outb = g_Wt + ((size_t)b * HW + p0) * NC + ny * 128;
#pragma unroll
    for (int mt = 0; mt < 4; mt++) {
        int pr = wm * 64 + mt * 16 + (lane >> 2);
#pragma unroll
        for (int nt = 0; nt < 4; nt++) {
            int nc = wn * 32 + nt * 8 + (lane & 3) * 2;
            float2 f0 = __half22float2(*(__half2*)&acc[mt][nt][0]);   // row pr
            float2 f1 = __half22float2(*(__half2*)&acc[mt][nt][1]);   // row pr+8
            *(__half2*)(outb + (size_t)pr * NC + nc) =
                __floats2half2_rn(1.f / (1.f + __expf(-f0.x)),
                                  1.f / (1.f + __expf(-f0.y)));
            *(__half2*)(outb + (size_t)(pr + 8) * NC + nc) =
                __floats2half2_rn(1.f / (1.f + __expf(-f1.x)),
                                  1.f / (1.f + __expf(-f1.y)));
        }
    }
}

// ---------------------------------------------------------------------------
// K2: selective warp-affine fill + softmax. 1 warp/pixel. fp16 in/out.
// Writes CENTERED weights d = w - 1/256 (GEMM2 A operand, tile-swizzled).
// ---------------------------------------------------------------------------
__global__ __launch_bounds__(256) void warp_softmax_kernel() {
    const int warp = threadIdx.x >> 5, lane = threadIdx.x & 31;
    const int g = blockIdx.x * 8 + warp;
    const int b = g / HW;
    const int p = g - b * HW;

    const __half* own = g_Wt + (size_t)g * NC;
    float v[8];
    {
        uint2 u0 = *(const uint2*)(own + lane * 4);
        uint2 u1 = *(const uint2*)(own + 128 + lane * 4);
        float2 f0 = __half22float2(*(__half2*)&u0.x), f1 = __half22float2(*(__half2*)&u0.y);
        float2 f2 = __half22float2(*(__half2*)&u1.x), f3 = __half22float2(*(__half2*)&u1.y);
        v[0] = f0.x; v[1] = f0.y; v[2] = f1.x; v[3] = f1.y;
        v[4] = f2.x; v[5] = f2.y; v[6] = f3.x; v[7] = f3.y;
    }

    if (b & 1) {   // agent > 0
        const int h = p / W_;
        const int w = p - h * W_;
        const float* th = g_theta[b];
        float gx = 2.f * (float)w / (float)(W_ - 1) - 1.f;
        float gy = 2.f * (float)h / (float)(H_ - 1) - 1.f;
        float cx2 = th[0] * gx + th[1] * gy + th[2];
        float cy2 = th[3] * gx + th[4] * gy + th[5];
        float x = (cx2 + 1.f) * (float)(W_ - 1) * 0.5f;
        float y = (cy2 + 1.f) * (float)(H_ - 1) * 0.5f;
        float x0f = floorf(x), y0f = floorf(y);
        int x0 = (int)x0f, y0 = (int)y0f;
        int x1 = x0 + 1,   y1 = y0 + 1;
        float fx = x - x0f, fy = y - y0f;
        bool vx0 = (x0 >= 0) && (x0 < W_), vx1 = (x1 >= 0) && (x1 < W_);
        bool vy0 = (y0 >= 0) && (y0 < H_), vy1 = (y1 >= 0) && (y1 < H_);
        float wa = (vx0 && vy0) ? (1.f - fx) * (1.f - fy) : 0.f;
        float wb = (vx1 && vy0) ? fx * (1.f - fy)         : 0.f;
        float wc = (vx0 && vy1) ? (1.f - fx) * fy         : 0.f;
        float wd = (vx1 && vy1) ? fx * fy                 : 0.f;
        int cx0 = min(max(x0, 0), W_ - 1), cx1 = min(max(x1, 0), W_ - 1);
        int cy0 = min(max(y0, 0), H_ - 1), cy1 = min(max(y1, 0), H_ - 1);

        const __half* ego = g_Wt + (size_t)(b - 1) * HW * NC;
        const __half* r00 = ego + (size_t)(cy0 * W_ + cx0) * NC;
        const __half* r10 = ego + (size_t)(cy0 * W_ + cx1) * NC;
        const __half* r01 = ego + (size_t)(cy1 * W_ + cx0) * NC;
        const __half* r11 = ego + (size_t)(cy1 * W_ + cx1) * NC;

        int4 m0 = *(const int4*)&g_masked[lane * 4];
        int4 m1 = *(const int4*)&g_masked[128 + lane * 4];
        int mk[8] = {m0.x, m0.y, m0.z, m0.w, m1.x, m1.y, m1.z, m1.w};

#pragma unroll
        for (int half = 0; half < 2; half++) {
            int off = half * 128 + lane * 4;
            uint2 ua = *(const uint2*)(r00 + off);
            uint2 uq = *(const uint2*)(r10 + off);
            uint2 uc = *(const uint2*)(r01 + off);
            uint2 ud = *(const uint2*)(r11 + off);
            float2 a0 = __half22float2(*(__half2*)&ua.x), a1 = __half22float2(*(__half2*)&ua.y);
            float2 q0 = __half22float2(*(__half2*)&uq.x), q1 = __half22float2(*(__half2*)&uq.y);
            float2 c0 = __half22float2(*(__half2*)&uc.x), c1 = __half22float2(*(__half2*)&uc.y);
            float2 d0 = __half22float2(*(__half2*)&ud.x), d1 = __half22float2(*(__half2*)&ud.y);
            float wv[4] = {
                wa * a0.x + wb * q0.x + wc * c0.x + wd * d0.x,
                wa * a0.y + wb * q0.y + wc * c0.y + wd * d0.y,
                wa * a1.x + wb * q1.x + wc * c1.x + wd * d1.x,
                wa * a1.y + wb * q1.y + wc * c1.y + wd * d1.y};
#pragma unroll
            for (int j = 0; j < 4; j++)
                if (mk[half * 4 + j]) v[half * 4 + j] = wv[j];
        }
    }

    float m = v[0];
#pragma unroll
    for (int j = 1; j < 8; j++) m = fmaxf(m, v[j]);
#pragma unroll
    for (int o = 16; o > 0; o >>= 1) m = fmaxf(m, __shfl_xor_sync(0xffffffffu, m, o));
    float e[8]; float s = 0.f;
#pragma unroll
    for (int j = 0; j < 8; j++) { e[j] = __expf(v[j] - m); s += e[j]; }
#pragma unroll
    for (int o = 16; o > 0; o >>= 1) s += __shfl_xor_sync(0xffffffffu, s, o);
    float inv = 1.f / s;

    // write CENTERED tile-swizzled fp16 (GEMM2 A layout): d = w - 1/256
    const float MU = 1.0f / 256.0f;
    const int pl = p & 127;
    const size_t tb = (size_t)(b * NTILE + (p >> 7)) * 32768;
#pragma unroll
    for (int grp = 0; grp < 2; grp++) {
        int n0 = grp * 128 + lane * 4;
        int st = n0 >> 6, nl = n0 & 63;
        size_t eidx = tb + (size_t)st * 8192 + (size_t)(swz(pl, 2 * nl) >> 1);
        *(__half2*)(g_WsTh + eidx)     = __floats2half2_rn(e[grp * 4 + 0] * inv - MU,
                                                           e[grp * 4 + 1] * inv - MU);
        *(__half2*)(g_WsTh + eidx + 2) = __floats2half2_rn(e[grp * 4 + 2] * inv - MU,
                                                           e[grp * 4 + 3] * inv - MU);
    }
}

// ---------------------------------------------------------------------------
// GEMM2: out[c][p] = sum_n d[p][n]*cb[n][c] + colsum[c]    (fp16 accumulate,
// d centered so partials are tiny -> fp16-acc precision is safe)
// CTA: 128p x 128c; grid (2, 144, 8). 2 CTAs/SM.
// ---------------------------------------------------------------------------
__global__ __launch_bounds__(256, 2) void gemm2_mma(float* __restrict__ out) {
    extern __shared__ char smem_raw[];
    uint32_t sb0 = smem_u32(smem_raw);
    uint32_t base = (sb0 + 127u) & ~127u;
    char* smem = smem_raw + (base - sb0);

    const int tid = threadIdx.x;
    const int lane = tid & 31, warp = tid >> 5;
    const int wm = warp >> 2;
    const int wn = warp & 3;
    const int b  = blockIdx.z;
    const int cy = blockIdx.x;       // c block (fastest: L2 pairing)
    const int p0 = blockIdx.y * 128;

    const char* srcA = (const char*)(g_WsTh + (size_t)(b * NTILE + blockIdx.y) * 32768);
    const char* srcB = (const char*)(g_B2h + cy * 32768);

    auto issue = [&](int s) {
        uint32_t dA = base + (s & 1) * 32768;
        uint32_t dB = dA + 16384;
#pragma unroll
        for (int k = 0; k < 4; k++) {
            int idx = tid + k * 256;
            CP16(dA + idx * 16, srcA + (size_t)s * 16384 + idx * 16);
        }
#pragma unroll
        for (int k = 0; k < 4; k++) {
            int idx = tid + k * 256;
            CP16(dB + idx * 16, srcB + (size_t)s * 16384 + idx * 16);
        }
        CP_COMMIT();
    };

    issue(0);
    issue(1);

    int rA_off[4], xmA[4];
#pragma unroll
    for (int mt = 0; mt < 4; mt++) {
        int r = wm * 64 + mt * 16 + (lane & 15);
        rA_off[mt] = r * 128;
        xmA[mt] = (r & 7) << 4;
    }
    const int cb0A = (lane >> 4) << 4;
    int rB_off[2], xmB[2];
#pragma unroll
    for (int g = 0; g < 2; g++) {
        int r = wn * 32 + g * 16 + ((lane >> 4) << 3) + (lane & 7);
        rB_off[g] = r * 128;
        xmB[g] = (r & 7) << 4;
    }
    const int cb0B = ((lane >> 3) & 1) << 4;

    uint32_t acc[4][4][2];
#pragma unroll
    for (int i = 0; i < 4; i++)
#pragma unroll
        for (int j = 0; j < 4; j++) { acc[i][j][0] = 0u; acc[i][j][1] = 0u; }

    for (int s = 0; s < 4; s++) {
        if (s < 3) CP_WAIT(1); else CP_WAIT(0);
        __syncthreads();

        const uint32_t Abuf = base + (s & 1) * 32768;
        const uint32_t Bbuf = Abuf + 16384;
#pragma unroll
        for (int ks = 0; ks < 4; ks++) {
            uint32_t a[4][4], bf[4][2];
#pragma unroll
            for (int mt = 0; mt < 4; mt++)
                LDSM4(a[mt][0], a[mt][1], a[mt][2], a[mt][3],
                      Abuf + rA_off[mt] + ((ks * 32 + cb0A) ^ xmA[mt]));
#pragma unroll
            for (int g = 0; g < 2; g++) {
                uint32_t r0, r1, r2, r3;
                LDSM4(r0, r1, r2, r3, Bbuf + rB_off[g] + ((ks * 32 + cb0B) ^ xmB[g]));
                bf[2 * g][0] = r0; bf[2 * g][1] = r1;
                bf[2 * g + 1][0] = r2; bf[2 * g + 1][1] = r3;
            }
#pragma unroll
            for (int mt = 0; mt < 4; mt++)
#pragma unroll
                for (int nt = 0; nt < 4; nt++)
                    MMA16816H(acc[mt][nt], a[mt][0], a[mt][1], a[mt][2], a[mt][3],
                              bf[nt][0], bf[nt][1]);
        }
        __syncthreads();
        if (s < 2) issue(s + 2);
    }

    // epilogue: add colsum (mean term), transpose (p,c)->E[c][p], coalesced stores
    float* E = (float*)smem;
#pragma unroll
    for (int mt = 0; mt < 4; mt++) {
        int pr = wm * 64 + mt * 16 + (lane >> 2);
#pragma unroll
        for (int nt = 0; nt < 4; nt++) {
            int cc = wn * 32 + nt * 8 + (lane & 3) * 2;
            float cs0 = g_colsum[cy * 128 + cc];
            float cs1 = g_colsum[cy * 128 + cc + 1];
            float2 f0 = __half22float2(*(__half2*)&acc[mt][nt][0]);   // row pr
            float2 f1 = __half22float2(*(__half2*)&acc[mt][nt][1]);   // row pr+8
            E[cc * 132 + pr]           = f0.x + cs0;
            E[(cc + 1) * 132 + pr]     = f0.y + cs1;
            E[cc * 132 + pr + 8]       = f1.x + cs0;
            E[(cc + 1) * 132 + pr + 8] = f1.y + cs1;
        }
    }
    __syncthreads();

    float* ob = out + ((size_t)b * CD + cy * 128) * HW + p0;
#pragma unroll
    for (int i = 0; i < 16; i++) {
        int idx = tid + i * 256;           // 128 c-rows x 32 float4
        int c = idx >> 5, q = idx & 31;
        float4 v = *(float4*)&E[c * 132 + q * 4];
        *(float4*)(ob + (size_t)c * HW + q * 4) = v;
    }
}

// ---------------------------------------------------------------------------
extern "C" void kernel_launch(void* const* d_in, const int* in_sizes, int n_in,
                              void* d_out, int out_size) {
    (void)in_sizes; (void)n_in; (void)out_size;
    const float* feat = (const float*)d_in[0];
    const float* cb   = (const float*)d_in[1];
    const float* pub  = (const float*)d_in[2];
    const float* aff  = (const float*)d_in[3];
    float* out = (float*)d_out;

    cudaFuncSetAttribute(gemm1_mma, cudaFuncAttributeMaxDynamicSharedMemorySize, 98432);
    cudaFuncSetAttribute(gemm2_mma, cudaFuncAttributeMaxDynamicSharedMemorySize, 67712);

    setup_kernel<<<NC, 256>>>(cb, pub, aff);
    prep_kernel<<<NC, 256>>>(cb);
    colsum_kernel<<<1, 256>>>(cb);

    gemm1_mma<<<dim3(2, NTILE, NB), 256, 98432>>>(feat);
    warp_softmax_kernel<<<NB * HW / 8, 256>>>();
    gemm2_mma<<<dim3(2, NTILE, NB), 256, 67712>>>(out);
}

// round 12
// speedup vs baseline: 1.0537x; 1.0537x over previous
#include <cuda_runtime.h>
#include <cuda_fp16.h>
#include <math.h>
#include <stdint.h>

#define B_   4
#define NB   8          // flattened images
#define NC   256        // codes
#define CD   256        // channels
#define H_   96
#define W_   192
#define HW   (H_*W_)    // 18432
#define NTILE 144       // HW/128

// ---------------- global scratch (.bss) ----------------
__device__ __align__(256) __half g_Wt[(size_t)NB * HW * NC];    // sigmoid weights [b][p][n] fp16
__device__ __align__(256) __half g_WsTh[(size_t)NB * HW * NC];  // centered softmax weights, tile-swizzled fp16
__device__ __align__(256) __half g_B1h[NC * CD];                // cb[n][c]/norm2[n], tiled
__device__ __align__(256) __half g_B2h[NC * CD];                // cb as rows c, k=n, tiled
__device__ float g_colsum[CD];                                  // (1/256)*sum_n cb[n][c]
__device__ float g_norm[NC];
__device__ int   g_masked[NC];
__device__ float g_theta[NB][6];

// ---------------- helpers ----------------
__device__ __forceinline__ uint32_t smem_u32(const void* p) {
    uint32_t a;
    asm("{ .reg .u64 t; cvta.to.shared.u64 t, %1; cvt.u32.u64 %0, t; }" : "=r"(a) : "l"(p));
    return a;
}

// SW128 swizzle: byte offset within a 128-row x 128-byte tile
__device__ __forceinline__ int swz(int row, int bytecol) {
    return row * 128 + (bytecol ^ ((row & 7) << 4));
}

#define LDSM4(d0, d1, d2, d3, a) \
    asm volatile("ldmatrix.sync.aligned.m8n8.x4.shared.b16 {%0,%1,%2,%3}, [%4];" \
                 : "=r"(d0), "=r"(d1), "=r"(d2), "=r"(d3) : "r"(a))

#define LDSM4T(d0, d1, d2, d3, a) \
    asm volatile("ldmatrix.sync.aligned.m8n8.x4.trans.shared.b16 {%0,%1,%2,%3}, [%4];" \
                 : "=r"(d0), "=r"(d1), "=r"(d2), "=r"(d3) : "r"(a))

// fp16-accumulate (both GEMMs — full-rate HMMA on sm_103a)
#define MMA16816H(d, a0, a1, a2, a3, b0, b1) \
    asm volatile("mma.sync.aligned.m16n8k16.row.col.f16.f16.f16.f16 " \
                 "{%0,%1}, {%2,%3,%4,%5}, {%6,%7}, {%0,%1};" \
                 : "+r"((d)[0]), "+r"((d)[1]) \
                 : "r"(a0), "r"(a1), "r"(a2), "r"(a3), "r"(b0), "r"(b1))

#define CP16(dst, src) \
    asm volatile("cp.async.cg.shared.global [%0], [%1], 16;" :: "r"(dst), "l"(src))
#define CP_COMMIT() asm volatile("cp.async.commit_group;" ::: "memory")
#define CP_WAIT(n)  asm volatile("cp.async.wait_group %0;" :: "n"(n) : "memory")

// ---------------------------------------------------------------------------
// Setup: per-code norm^2, cosine mask, theta copy. Warp-coalesced pub scan.
// ---------------------------------------------------------------------------
__global__ __launch_bounds__(256) void setup_kernel(const float* __restrict__ cb,
                                                    const float* __restrict__ pub,
                                                    const float* __restrict__ aff) {
    __shared__ float cbrow[256];
    __shared__ float sqs[8];
    __shared__ float wmaxs[8];
    const int n = blockIdx.x, t = threadIdx.x;
    const int w = t >> 5, l = t & 31;

    float v = cb[n * CD + t];
    cbrow[t] = v;
    float sq = v * v;
#pragma unroll
    for (int o = 16; o > 0; o >>= 1) sq += __shfl_xor_sync(0xffffffffu, sq, o);
    if (l == 0) sqs[w] = sq;
    __syncthreads();
    float cbn2 = 0.f;
#pragma unroll
    for (int i = 0; i < 8; i++) cbn2 += sqs[i];

    float wmax = -1e30f;
    for (int i = 0; i < 32; i++) {
        const int r = w * 32 + i;
        const float* pr = pub + r * CD + l * 8;
        const float* cr = cbrow + l * 8;
        float dot = 0.f, pn2 = 0.f;
#pragma unroll
        for (int j = 0; j < 2; j++) {
            float4 p4 = *(const float4*)(pr + j * 4);
            float4 c4 = *(const float4*)(cr + j * 4);
            dot += p4.x * c4.x + p4.y * c4.y + p4.z * c4.z + p4.w * c4.w;
            pn2 += p4.x * p4.x + p4.y * p4.y + p4.z * p4.z + p4.w * p4.w;
        }
#pragma unroll
        for (int o = 16; o > 0; o >>= 1) {
            dot += __shfl_xor_sync(0xffffffffu, dot, o);
            pn2 += __shfl_xor_sync(0xffffffffu, pn2, o);
        }
        wmax = fmaxf(wmax, dot * rsqrtf(cbn2 * pn2));
    }
    if (l == 0) wmaxs[w] = wmax;
    __syncthreads();
    if (t == 0) {
        float m = wmaxs[0];
#pragma unroll
        for (int i = 1; i < 8; i++) m = fmaxf(m, wmaxs[i]);
        g_masked[n] = (m <= 0.5f) ? 1 : 0;
        g_norm[n]   = cbn2;
    }
    if (n == 0 && t < NB * 6) g_theta[t / 6][t % 6] = aff[(t / 6) * 12 + (t % 6)];
}

// ---------------------------------------------------------------------------
// Prep: fp16 pre-swizzled operands + column-sum for the mean term.
// ---------------------------------------------------------------------------
__global__ __launch_bounds__(256) void prep_kernel(const float* __restrict__ cb) {
    const int r = blockIdx.x, t = threadIdx.x;
    const float inv = 1.f / g_norm[r];

    {   // B1: row n=r, k=c=t
        float x = cb[r * CD + t] * inv;
        int e = (r >> 7) * 32768 + (t >> 6) * 8192 + (swz(r & 127, 2 * (t & 63)) >> 1);
        g_B1h[e] = __float2half(x);
    }
    {   // B2: row c=r, k=n=t
        float x = cb[t * CD + r];
        int e = (r >> 7) * 32768 + (t >> 6) * 8192 + (swz(r & 127, 2 * (t & 63)) >> 1);
        g_B2h[e] = __float2half(x);
    }
}

// colsum[c] = (1/256) * sum_n cb[n][c]
__global__ __launch_bounds__(256) void colsum_kernel(const float* __restrict__ cb) {
    const int c = threadIdx.x;
    float s = 0.f;
#pragma unroll 8
    for (int n = 0; n < NC; n++) s += cb[n * CD + c];
    g_colsum[c] = s * (1.0f / 256.0f);
}

// ---------------------------------------------------------------------------
// GEMM1: Wt[p][n] = sigmoid( sum_c feat[c][p] * cb[n][c] / norm2[n] )
// A kept untransposed in smem ([c-rows][128 p halves], 256B rows, XOR swizzle);
// A fragments via ldmatrix.trans. float4 feat loads. fp16 accumulators.
// CTA: 128p x 128n; grid (2, 144, 8); 2 CTAs/SM.
// smem: B 4x16KB @0, A 2x16KB @65536.
// ---------------------------------------------------------------------------
__global__ __launch_bounds__(256, 2) void gemm1_mma(const float* __restrict__ feat) {
    extern __shared__ char smem_raw[];
    uint32_t sb0 = smem_u32(smem_raw);
    uint32_t base = (sb0 + 127u) & ~127u;
    char* smem = smem_raw + (base - sb0);

    const int tid = threadIdx.x;
    const int lane = tid & 31, warp = tid >> 5;
    const int wm = warp >> 2;        // 0..1 -> m offset wm*64
    const int wn = warp & 3;         // 0..3 -> n offset wn*32
    const int b  = blockIdx.z;
    const int ny = blockIdx.x;       // n block 0/1 (fastest: L2 pairing)
    const int p0 = blockIdx.y * 128;

    // issue all B stage copies (4 groups)
    {
        const char* src = (const char*)(g_B1h + ny * 32768);
#pragma unroll
        for (int s = 0; s < 4; s++) {
#pragma unroll
            for (int k = 0; k < 4; k++) {
                int idx = tid + k * 256;
                CP16(base + s * 16384 + idx * 16, src + s * 16384 + idx * 16);
            }
            CP_COMMIT();
        }
    }

    // A (trans) ldmatrix per-lane base offsets within a k16-chunk
    // lanes 0-7: k0-7/m+0 (a0); 8-15: k0-7/m+8 (a1); 16-23: k8-15/m+0 (a2); 24-31: k8-15/m+8 (a3)
    int aoff[4];
    {
        int krb  = (lane & 7) + ((lane >> 4) & 1) * 8;       // 0..15
        int moff = ((lane >> 3) & 1) * 8;                     // 0 or 8
#pragma unroll
        for (int mt = 0; mt < 4; mt++) {
            int mcol = wm * 64 + mt * 16 + moff;
            aoff[mt] = krb * 256 + ((mcol * 2) ^ ((krb & 7) << 4));
        }
    }
    // B ldmatrix addresses (unchanged, 128B-row SW128 tile)
    int rB_off[2], xmB[2];
#pragma unroll
    for (int g = 0; g < 2; g++) {
        int r = wn * 32 + g * 16 + ((lane >> 4) << 3) + (lane & 7);
        rB_off[g] = r * 128;
        xmB[g] = (r & 7) << 4;
    }
    const int cb0B = ((lane >> 3) & 1) << 4;

    uint32_t acc[4][4][2];
#pragma unroll
    for (int i = 0; i < 4; i++)
#pragma unroll
        for (int j = 0; j < 4; j++) { acc[i][j][0] = 0u; acc[i][j][1] = 0u; }

    const float* fbase = feat + (size_t)b * CD * HW + p0;
    const int frow = tid >> 5;           // 0..7 base c row (of 64, step 8)... see loop
    const int fc4  = (tid & 31) * 4;     // float col within 128
    float4 fr[8];

    // A stage store: row r holds p-halves, 256B row, XOR-swizzled 8B units
    auto storeA = [&](char* An) {
#pragma unroll
        for (int i = 0; i < 8; i++) {
            int r = frow + i * 8;        // 0..63
            __half2 h[2];
            h[0] = __floats2half2_rn(fr[i].x, fr[i].y);
            h[1] = __floats2half2_rn(fr[i].z, fr[i].w);
            int colb = (fc4 * 2) ^ ((r & 7) << 4);
            *(uint2*)(An + r * 256 + colb) = *(uint2*)h;
        }
    };
    auto loadA = [&](int s) {
        const float* fs = fbase + (size_t)(s * 64) * HW;
#pragma unroll
        for (int i = 0; i < 8; i++) {
            int r = frow + i * 8;
            fr[i] = *(const float4*)(fs + (size_t)r * HW + fc4);
        }
    };

    // prologue: stage 0 A
    loadA(0);
    storeA(smem + 65536);

    for (int s = 0; s < 4; s++) {
        if (s < 3) loadA(s + 1);          // overlap LDG with MMA section below
        if (s == 0) CP_WAIT(3);
        else if (s == 1) CP_WAIT(2);
        else if (s == 2) CP_WAIT(1);
        else CP_WAIT(0);
        __syncthreads();

        const uint32_t Abuf = base + 65536 + (s & 1) * 16384;
        const uint32_t Bst  = base + s * 16384;
#pragma unroll
        for (int ks = 0; ks < 4; ks++) {
            uint32_t a[4][4], bf[4][2];
#pragma unroll
            for (int mt = 0; mt < 4; mt++)
                LDSM4T(a[mt][0], a[mt][1], a[mt][2], a[mt][3],
                       Abuf + ks * 4096 + aoff[mt]);
#pragma unroll
            for (int g = 0; g < 2; g++) {
                uint32_t r0, r1, r2, r3;
                LDSM4(r0, r1, r2, r3, Bst + rB_off[g] + ((ks * 32 + cb0B) ^ xmB[g]));
                bf[2 * g][0] = r0; bf[2 * g][1] = r1;
                bf[2 * g + 1][0] = r2; bf[2 * g + 1][1] = r3;
            }
#pragma unroll
            for (int mt = 0; mt < 4; mt++)
#pragma unroll
                for (int nt = 0; nt < 4; nt++)
                    MMA16816H(acc[mt][nt], a[mt][0], a[mt][1], a[mt][2], a[mt][3],
                              bf[nt][0], bf[nt][1]);
        }

        if (s < 3) storeA(smem + 65536 + ((s + 1) & 1) * 16384);
        __syncthreads();
    }

    // epilogue: sigmoid + fp16 STG (rows p, contiguous n)
    __half* outb = g_Wt + ((size_t)b * HW + p0) * NC + ny * 128;
#pragma unroll
    for (int mt = 0; mt < 4; mt++) {
        int pr = wm * 64 + mt * 16 + (lane >> 2);
#pragma unroll
        for (int nt = 0; nt < 4; nt++) {
            int nc = wn * 32 + nt * 8 + (lane & 3) * 2;
            float2 f0 = __half22float2(*(__half2*)&acc[mt][nt][0]);   // row pr
            float2 f1 = __half22float2(*(__half2*)&acc[mt][nt][1]);   // row pr+8
            *(__half2*)(outb + (size_t)pr * NC + nc) =
                __floats2half2_rn(1.f / (1.f + __expf(-f0.x)),
                                  1.f / (1.f + __expf(-f0.y)));
            *(__half2*)(outb + (size_t)(pr + 8) * NC + nc) =
                __floats2half2_rn(1.f / (1.f + __expf(-f1.x)),
                                  1.f / (1.f + __expf(-f1.y)));
        }
    }
}

// ---------------------------------------------------------------------------
// K2: selective warp-affine fill + softmax. 1 warp/pixel. fp16 in/out.
// Writes CENTERED weights d = w - 1/256 (GEMM2 A operand, tile-swizzled).
// ---------------------------------------------------------------------------
__global__ __launch_bounds__(256) void warp_softmax_kernel() {
    const int warp = threadIdx.x >> 5, lane = threadIdx.x & 31;
    const int g = blockIdx.x * 8 + warp;
    const int b = g / HW;
    const int p = g - b * HW;

    const __half* own = g_Wt + (size_t)g * NC;
    float v[8];
    {
        uint2 u0 = *(const uint2*)(own + lane * 4);
        uint2 u1 = *(const uint2*)(own + 128 + lane * 4);
        float2 f0 = __half22float2(*(__half2*)&u0.x), f1 = __half22float2(*(__half2*)&u0.y);
        float2 f2 = __half22float2(*(__half2*)&u1.x), f3 = __half22float2(*(__half2*)&u1.y);
        v[0] = f0.x; v[1] = f0.y; v[2] = f1.x; v[3] = f1.y;
        v[4] = f2.x; v[5] = f2.y; v[6] = f3.x; v[7] = f3.y;
    }

    if (b & 1) {   // agent > 0
        const int h = p / W_;
        const int w = p - h * W_;
        const float* th = g_theta[b];
        float gx = 2.f * (float)w / (float)(W_ - 1) - 1.f;
        float gy = 2.f * (float)h / (float)(H_ - 1) - 1.f;
        float cx2 = th[0] * gx + th[1] * gy + th[2];
        float cy2 = th[3] * gx + th[4] * gy + th[5];
        float x = (cx2 + 1.f) * (float)(W_ - 1) * 0.5f;
        float y = (cy2 + 1.f) * (float)(H_ - 1) * 0.5f;
        float x0f = floorf(x), y0f = floorf(y);
        int x0 = (int)x0f, y0 = (int)y0f;
        int x1 = x0 + 1,   y1 = y0 + 1;
        float fx = x - x0f, fy = y - y0f;
        bool vx0 = (x0 >= 0) && (x0 < W_), vx1 = (x1 >= 0) && (x1 < W_);
        bool vy0 = (y0 >= 0) && (y0 < H_), vy1 = (y1 >= 0) && (y1 < H_);
        float wa = (vx0 && vy0) ? (1.f - fx) * (1.f - fy) : 0.f;
        float wb = (vx1 && vy0) ? fx * (1.f - fy)         : 0.f;
        float wc = (vx0 && vy1) ? (1.f - fx) * fy         : 0.f;
        float wd = (vx1 && vy1) ? fx * fy                 : 0.f;
        int cx0 = min(max(x0, 0), W_ - 1), cx1 = min(max(x1, 0), W_ - 1);
        int cy0 = min(max(y0, 0), H_ - 1), cy1 = min(max(y1, 0), H_ - 1);

        const __half* ego = g_Wt + (size_t)(b - 1) * HW * NC;
        const __half* r00 = ego + (size_t)(cy0 * W_ + cx0) * NC;
        const __half* r10 = ego + (size_t)(cy0 * W_ + cx1) * NC;
        const __half* r01 = ego + (size_t)(cy1 * W_ + cx0) * NC;
        const __half* r11 = ego + (size_t)(cy1 * W_ + cx1) * NC;

        int4 m0 = *(const int4*)&g_masked[lane * 4];
        int4 m1 = *(const int4*)&g_masked[128 + lane * 4];
        int mk[8] = {m0.x, m0.y, m0.z, m0.w, m1.x, m1.y, m1.z, m1.w};

#pragma unroll
        for (int half = 0; half < 2; half++) {
            int off = half * 128 + lane * 4;
            uint2 ua = *(const uint2*)(r00 + off);
            uint2 uq = *(const uint2*)(r10 + off);
            uint2 uc = *(const uint2*)(r01 + off);
            uint2 ud = *(const uint2*)(r11 + off);
            float2 a0 = __half22float2(*(__half2*)&ua.x), a1 = __half22float2(*(__half2*)&ua.y);
            float2 q0 = __half22float2(*(__half2*)&uq.x), q1 = __half22float2(*(__half2*)&uq.y);
            float2 c0 = __half22float2(*(__half2*)&uc.x), c1 = __half22float2(*(__half2*)&uc.y);
            float2 d0 = __half22float2(*(__half2*)&ud.x), d1 = __half22float2(*(__half2*)&ud.y);
            float wv[4] = {
                wa * a0.x + wb * q0.x + wc * c0.x + wd * d0.x,
                wa * a0.y + wb * q0.y + wc * c0.y + wd * d0.y,
                wa * a1.x + wb * q1.x + wc * c1.x + wd * d1.x,
                wa * a1.y + wb * q1.y + wc * c1.y + wd * d1.y};
#pragma unroll
            for (int j = 0; j < 4; j++)
                if (mk[half * 4 + j]) v[half * 4 + j] = wv[j];
        }
    }

    float m = v[0];
#pragma unroll
    for (int j = 1; j < 8; j++) m = fmaxf(m, v[j]);
#pragma unroll
    for (int o = 16; o > 0; o >>= 1) m = fmaxf(m, __shfl_xor_sync(0xffffffffu, m, o));
    float e[8]; float s = 0.f;
#pragma unroll
    for (int j = 0; j < 8; j++) { e[j] = __expf(v[j] - m); s += e[j]; }
#pragma unroll
    for (int o = 16; o > 0; o >>= 1) s += __shfl_xor_sync(0xffffffffu, s, o);
    float inv = 1.f / s;

    // write CENTERED tile-swizzled fp16 (GEMM2 A layout): d = w - 1/256
    const float MU = 1.0f / 256.0f;
    const int pl = p & 127;
    const size_t tb = (size_t)(b * NTILE + (p >> 7)) * 32768;
#pragma unroll
    for (int grp = 0; grp < 2; grp++) {
        int n0 = grp * 128 + lane * 4;
        int st = n0 >> 6, nl = n0 & 63;
        size_t eidx = tb + (size_t)st * 8192 + (size_t)(swz(pl, 2 * nl) >> 1);
        *(__half2*)(g_WsTh + eidx)     = __floats2half2_rn(e[grp * 4 + 0] * inv - MU,
                                                           e[grp * 4 + 1] * inv - MU);
        *(__half2*)(g_WsTh + eidx + 2) = __floats2half2_rn(e[grp * 4 + 2] * inv - MU,
                                                           e[grp * 4 + 3] * inv - MU);
    }
}

// ---------------------------------------------------------------------------
// GEMM2: out[c][p] = sum_n d[p][n]*cb[n][c] + colsum[c]    (fp16 accumulate,
// d centered so partials are tiny -> fp16-acc precision is safe)
// CTA: 128p x 128c; grid (2, 144, 8). 2 CTAs/SM.
// ---------------------------------------------------------------------------
__global__ __launch_bounds__(256, 2) void gemm2_mma(float* __restrict__ out) {
    extern __shared__ char smem_raw[];
    uint32_t sb0 = smem_u32(smem_raw);
    uint32_t base = (sb0 + 127u) & ~127u;
    char* smem = smem_raw + (base - sb0);

    const int tid = threadIdx.x;
    const int lane = tid & 31, warp = tid >> 5;
    const int wm = warp >> 2;
    const int wn = warp & 3;
    const int b  = blockIdx.z;
    const int cy = blockIdx.x;       // c block (fastest: L2 pairing)
    const int p0 = blockIdx.y * 128;

    const char* srcA = (const char*)(g_WsTh + (size_t)(b * NTILE + blockIdx.y) * 32768);
    const char* srcB = (const char*)(g_B2h + cy * 32768);

    auto issue = [&](int s) {
        uint32_t dA = base + (s & 1) * 32768;
        uint32_t dB = dA + 16384;
#pragma unroll
        for (int k = 0; k < 4; k++) {
            int idx = tid + k * 256;
            CP16(dA + idx * 16, srcA + (size_t)s * 16384 + idx * 16);
        }
#pragma unroll
        for (int k = 0; k < 4; k++) {
            int idx = tid + k * 256;
            CP16(dB + idx * 16, srcB + (size_t)s * 16384 + idx * 16);
        }
        CP_COMMIT();
    };

    issue(0);
    issue(1);

    int rA_off[4], xmA[4];
#pragma unroll
    for (int mt = 0; mt < 4; mt++) {
        int r = wm * 64 + mt * 16 + (lane & 15);
        rA_off[mt] = r * 128;
        xmA[mt] = (r & 7) << 4;
    }
    const int cb0A = (lane >> 4) << 4;
    int rB_off[2], xmB[2];
#pragma unroll
    for (int g = 0; g < 2; g++) {
        int r = wn * 32 + g * 16 + ((lane >> 4) << 3) + (lane & 7);
        rB_off[g] = r * 128;
        xmB[g] = (r & 7) << 4;
    }
    const int cb0B = ((lane >> 3) & 1) << 4;

    uint32_t acc[4][4][2];
#pragma unroll
    for (int i = 0; i < 4; i++)
#pragma unroll
        for (int j = 0; j < 4; j++) { acc[i][j][0] = 0u; acc[i][j][1] = 0u; }

    for (int s = 0; s < 4; s++) {
        if (s < 3) CP_WAIT(1); else CP_WAIT(0);
        __syncthreads();

        const uint32_t Abuf = base + (s & 1) * 32768;
        const uint32_t Bbuf = Abuf + 16384;
#pragma unroll
        for (int ks = 0; ks < 4; ks++) {
            uint32_t a[4][4], bf[4][2];
#pragma unroll
            for (int mt = 0; mt < 4; mt++)
                LDSM4(a[mt][0], a[mt][1], a[mt][2], a[mt][3],
                      Abuf + rA_off[mt] + ((ks * 32 + cb0A) ^ xmA[mt]));
#pragma unroll
            for (int g = 0; g < 2; g++) {
                uint32_t r0, r1, r2, r3;
                LDSM4(r0, r1, r2, r3, Bbuf + rB_off[g] + ((ks * 32 + cb0B) ^ xmB[g]));
                bf[2 * g][0] = r0; bf[2 * g][1] = r1;
                bf[2 * g + 1][0] = r2; bf[2 * g + 1][1] = r3;
            }
#pragma unroll
            for (int mt = 0; mt < 4; mt++)
#pragma unroll
                for (int nt = 0; nt < 4; nt++)
                    MMA16816H(acc[mt][nt], a[mt][0], a[mt][1], a[mt][2], a[mt][3],
                              bf[nt][0], bf[nt][1]);
        }
        __syncthreads();
        if (s < 2) issue(s + 2);
    }

    // epilogue: add colsum (mean term), transpose (p,c)->E[c][p], coalesced stores
    float* E = (float*)smem;
#pragma unroll
    for (int mt = 0; mt < 4; mt++) {
        int pr = wm * 64 + mt * 16 + (lane >> 2);
#pragma unroll
        for (int nt = 0; nt < 4; nt++) {
            int cc = wn * 32 + nt * 8 + (lane & 3) * 2;
            float cs0 = g_colsum[cy * 128 + cc];
            float cs1 = g_colsum[cy * 128 + cc + 1];
            float2 f0 = __half22float2(*(__half2*)&acc[mt][nt][0]);   // row pr
            float2 f1 = __half22float2(*(__half2*)&acc[mt][nt][1]);   // row pr+8
            E[cc * 132 + pr]           = f0.x + cs0;
            E[(cc + 1) * 132 + pr]     = f0.y + cs1;
            E[cc * 132 + pr + 8]       = f1.x + cs0;
            E[(cc + 1) * 132 + pr + 8] = f1.y + cs1;
        }
    }
    __syncthreads();

    float* ob = out + ((size_t)b * CD + cy * 128) * HW + p0;
#pragma unroll
    for (int i = 0; i < 16; i++) {
        int idx = tid + i * 256;           // 128 c-rows x 32 float4
        int c = idx >> 5, q = idx & 31;
        float4 v = *(float4*)&E[c * 132 + q * 4];
        *(float4*)(ob + (size_t)c * HW + q * 4) = v;
    }
}

// ---------------------------------------------------------------------------
extern "C" void kernel_launch(void* const* d_in, const int* in_sizes, int n_in,
                              void* d_out, int out_size) {
    (void)in_sizes; (void)n_in; (void)out_size;
    const float* feat = (const float*)d_in[0];
    const float* cb   = (const float*)d_in[1];
    const float* pub  = (const float*)d_in[2];
    const float* aff  = (const float*)d_in[3];
    float* out = (float*)d_out;

    cudaFuncSetAttribute(gemm1_mma, cudaFuncAttributeMaxDynamicSharedMemorySize, 98432);
    cudaFuncSetAttribute(gemm2_mma, cudaFuncAttributeMaxDynamicSharedMemorySize, 67712);

    setup_kernel<<<NC, 256>>>(cb, pub, aff);
    prep_kernel<<<NC, 256>>>(cb);
    colsum_kernel<<<1, 256>>>(cb);

    gemm1_mma<<<dim3(2, NTILE, NB), 256, 98432>>>(feat);
    warp_softmax_kernel<<<NB * HW / 8, 256>>>();
    gemm2_mma<<<dim3(2, NTILE, NB), 256, 67712>>>(out);
}

// round 13
// speedup vs baseline: 1.1699x; 1.1103x over previous
#include <cuda_runtime.h>
#include <cuda_fp16.h>
#include <math.h>
#include <stdint.h>

#define B_   4
#define NB   8          // flattened images
#define NC   256        // codes
#define CD   256        // channels
#define H_   96
#define W_   192
#define HW   (H_*W_)    // 18432
#define NTILE 144       // HW/128

// ---------------- global scratch (.bss) ----------------
__device__ __align__(256) __half g_Wt[(size_t)NB * HW * NC];    // sigmoid weights [b][p][n] fp16
__device__ __align__(256) __half g_WsTh[(size_t)NB * HW * NC];  // centered softmax weights, tile-swizzled fp16
__device__ __align__(256) __half g_B1h[NC * CD];                // cb[n][c]/norm2[n], tiled
__device__ __align__(256) __half g_B2h[NC * CD];                // cb as rows c, k=n, tiled
__device__ float g_colsum[CD];                                  // (1/256)*sum_n cb[n][c]
__device__ float g_norm[NC];
__device__ int   g_masked[NC];
__device__ float g_theta[NB][6];

// ---------------- helpers ----------------
__device__ __forceinline__ uint32_t smem_u32(const void* p) {
    uint32_t a;
    asm("{ .reg .u64 t; cvta.to.shared.u64 t, %1; cvt.u32.u64 %0, t; }" : "=r"(a) : "l"(p));
    return a;
}

// SW128 swizzle: byte offset within a 128-row x 128-byte tile
__device__ __forceinline__ int swz(int row, int bytecol) {
    return row * 128 + (bytecol ^ ((row & 7) << 4));
}

#define LDSM4(d0, d1, d2, d3, a) \
    asm volatile("ldmatrix.sync.aligned.m8n8.x4.shared.b16 {%0,%1,%2,%3}, [%4];" \
                 : "=r"(d0), "=r"(d1), "=r"(d2), "=r"(d3) : "r"(a))

#define LDSM4T(d0, d1, d2, d3, a) \
    asm volatile("ldmatrix.sync.aligned.m8n8.x4.trans.shared.b16 {%0,%1,%2,%3}, [%4];" \
                 : "=r"(d0), "=r"(d1), "=r"(d2), "=r"(d3) : "r"(a))

// fp16-accumulate (both GEMMs — full-rate HMMA on sm_103a)
#define MMA16816H(d, a0, a1, a2, a3, b0, b1) \
    asm volatile("mma.sync.aligned.m16n8k16.row.col.f16.f16.f16.f16 " \
                 "{%0,%1}, {%2,%3,%4,%5}, {%6,%7}, {%0,%1};" \
                 : "+r"((d)[0]), "+r"((d)[1]) \
                 : "r"(a0), "r"(a1), "r"(a2), "r"(a3), "r"(b0), "r"(b1))

#define CP16(dst, src) \
    asm volatile("cp.async.cg.shared.global [%0], [%1], 16;" :: "r"(dst), "l"(src))
#define CP_COMMIT() asm volatile("cp.async.commit_group;" ::: "memory")
#define CP_WAIT(n)  asm volatile("cp.async.wait_group %0;" :: "n"(n) : "memory")

// ---------------------------------------------------------------------------
// Setup: per-code norm^2, cosine mask, theta copy. Warp-coalesced pub scan.
// ---------------------------------------------------------------------------
__global__ __launch_bounds__(256) void setup_kernel(const float* __restrict__ cb,
                                                    const float* __restrict__ pub,
                                                    const float* __restrict__ aff) {
    __shared__ float cbrow[256];
    __shared__ float sqs[8];
    __shared__ float wmaxs[8];
    const int n = blockIdx.x, t = threadIdx.x;
    const int w = t >> 5, l = t & 31;

    float v = cb[n * CD + t];
    cbrow[t] = v;
    float sq = v * v;
#pragma unroll
    for (int o = 16; o > 0; o >>= 1) sq += __shfl_xor_sync(0xffffffffu, sq, o);
    if (l == 0) sqs[w] = sq;
    __syncthreads();
    float cbn2 = 0.f;
#pragma unroll
    for (int i = 0; i < 8; i++) cbn2 += sqs[i];

    float wmax = -1e30f;
    for (int i = 0; i < 32; i++) {
        const int r = w * 32 + i;
        const float* pr = pub + r * CD + l * 8;
        const float* cr = cbrow + l * 8;
        float dot = 0.f, pn2 = 0.f;
#pragma unroll
        for (int j = 0; j < 2; j++) {
            float4 p4 = *(const float4*)(pr + j * 4);
            float4 c4 = *(const float4*)(cr + j * 4);
            dot += p4.x * c4.x + p4.y * c4.y + p4.z * c4.z + p4.w * c4.w;
            pn2 += p4.x * p4.x + p4.y * p4.y + p4.z * p4.z + p4.w * p4.w;
        }
#pragma unroll
        for (int o = 16; o > 0; o >>= 1) {
            dot += __shfl_xor_sync(0xffffffffu, dot, o);
            pn2 += __shfl_xor_sync(0xffffffffu, pn2, o);
        }
        wmax = fmaxf(wmax, dot * rsqrtf(cbn2 * pn2));
    }
    if (l == 0) wmaxs[w] = wmax;
    __syncthreads();
    if (t == 0) {
        float m = wmaxs[0];
#pragma unroll
        for (int i = 1; i < 8; i++) m = fmaxf(m, wmaxs[i]);
        g_masked[n] = (m <= 0.5f) ? 1 : 0;
        g_norm[n]   = cbn2;
    }
    if (n == 0 && t < NB * 6) g_theta[t / 6][t % 6] = aff[(t / 6) * 12 + (t % 6)];
}

// ---------------------------------------------------------------------------
// Prep: fp16 pre-swizzled operands + fused column-sum (mean term).
// ---------------------------------------------------------------------------
__global__ __launch_bounds__(256) void prep_kernel(const float* __restrict__ cb) {
    __shared__ float red[8];
    const int r = blockIdx.x, t = threadIdx.x;
    const float inv = 1.f / g_norm[r];

    {   // B1: row n=r, k=c=t
        float x = cb[r * CD + t] * inv;
        int e = (r >> 7) * 32768 + (t >> 6) * 8192 + (swz(r & 127, 2 * (t & 63)) >> 1);
        g_B1h[e] = __float2half(x);
    }
    float x2 = cb[t * CD + r];
    {   // B2: row c=r, k=n=t
        int e = (r >> 7) * 32768 + (t >> 6) * 8192 + (swz(r & 127, 2 * (t & 63)) >> 1);
        g_B2h[e] = __float2half(x2);
    }
    // colsum[r] = (1/256) sum_t cb[t][r]
    float s = x2;
#pragma unroll
    for (int o = 16; o > 0; o >>= 1) s += __shfl_xor_sync(0xffffffffu, s, o);
    if ((t & 31) == 0) red[t >> 5] = s;
    __syncthreads();
    if (t == 0) {
        float cs = 0.f;
#pragma unroll
        for (int i = 0; i < 8; i++) cs += red[i];
        g_colsum[r] = cs * (1.0f / 256.0f);
    }
}

// ---------------------------------------------------------------------------
// GEMM1: Wt[p][n] = sigmoid( sum_c feat[c][p] * cb[n][c] / norm2[n] )
// 3 CTAs/SM. B cp.async double-buffered (2x16KB @0); A LDG->cvt->STS inline
// double-buffered (2x16KB @32768). A frags via ldmatrix.trans.
// CTA: 128p x 128n; grid (2, 144, 8).
// ---------------------------------------------------------------------------
__global__ __launch_bounds__(256, 3) void gemm1_mma(const float* __restrict__ feat) {
    extern __shared__ char smem_raw[];
    uint32_t sb0 = smem_u32(smem_raw);
    uint32_t base = (sb0 + 127u) & ~127u;
    char* smem = smem_raw + (base - sb0);

    const int tid = threadIdx.x;
    const int lane = tid & 31, warp = tid >> 5;
    const int wm = warp >> 2;        // 0..1 -> m offset wm*64
    const int wn = warp & 3;         // 0..3 -> n offset wn*32
    const int b  = blockIdx.z;
    const int ny = blockIdx.x;       // n block 0/1 (fastest: L2 pairing)
    const int p0 = blockIdx.y * 128;

    const char* srcB = (const char*)(g_B1h + ny * 32768);
    auto issueB = [&](int s) {
        uint32_t dB = base + (s & 1) * 16384;
#pragma unroll
        for (int k = 0; k < 4; k++) {
            int idx = tid + k * 256;
            CP16(dB + idx * 16, srcB + (size_t)s * 16384 + idx * 16);
        }
        CP_COMMIT();
    };

    const float* fbase = feat + (size_t)b * CD * HW + p0;
    auto loadStoreA = [&](int s) {
        const float* fs = fbase + (size_t)(s * 64) * HW;
        char* An = smem + 32768 + (s & 1) * 16384;
        const int fc = (tid & 31) * 4;
        const int colb0 = (tid & 31) * 8;
#pragma unroll
        for (int i = 0; i < 8; i++) {
            int r = (tid >> 5) + i * 8;          // 0..63
            float4 f = *(const float4*)(fs + (size_t)r * HW + fc);
            __half2 h0 = __floats2half2_rn(f.x, f.y);
            __half2 h1 = __floats2half2_rn(f.z, f.w);
            uint2 u; u.x = *(uint32_t*)&h0; u.y = *(uint32_t*)&h1;
            *(uint2*)(An + r * 256 + (colb0 ^ ((r & 7) << 4))) = u;
        }
    };

    // A (trans) ldmatrix per-lane base offsets within a k16-chunk
    int aoff[4];
    {
        int krb  = (lane & 7) + ((lane >> 4) & 1) * 8;       // 0..15
        int moff = ((lane >> 3) & 1) * 8;                     // 0 or 8
#pragma unroll
        for (int mt = 0; mt < 4; mt++) {
            int mcol = wm * 64 + mt * 16 + moff;
            aoff[mt] = krb * 256 + ((mcol * 2) ^ ((krb & 7) << 4));
        }
    }
    // B ldmatrix addresses (128B-row SW128 tile)
    int rB_off[2], xmB[2];
#pragma unroll
    for (int g = 0; g < 2; g++) {
        int r = wn * 32 + g * 16 + ((lane >> 4) << 3) + (lane & 7);
        rB_off[g] = r * 128;
        xmB[g] = (r & 7) << 4;
    }
    const int cb0B = ((lane >> 3) & 1) << 4;

    uint32_t acc[4][4][2];
#pragma unroll
    for (int i = 0; i < 4; i++)
#pragma unroll
        for (int j = 0; j < 4; j++) { acc[i][j][0] = 0u; acc[i][j][1] = 0u; }

    // prologue
    issueB(0);
    issueB(1);
    loadStoreA(0);
    CP_WAIT(1);
    __syncthreads();

    for (int s = 0; s < 4; s++) {
        const uint32_t Abuf = base + 32768 + (s & 1) * 16384;
        const uint32_t Bst  = base + (s & 1) * 16384;
#pragma unroll
        for (int ks = 0; ks < 4; ks++) {
            uint32_t a[4][4], bf[4][2];
#pragma unroll
            for (int mt = 0; mt < 4; mt++)
                LDSM4T(a[mt][0], a[mt][1], a[mt][2], a[mt][3],
                       Abuf + ks * 4096 + aoff[mt]);
#pragma unroll
            for (int g = 0; g < 2; g++) {
                uint32_t r0, r1, r2, r3;
                LDSM4(r0, r1, r2, r3, Bst + rB_off[g] + ((ks * 32 + cb0B) ^ xmB[g]));
                bf[2 * g][0] = r0; bf[2 * g][1] = r1;
                bf[2 * g + 1][0] = r2; bf[2 * g + 1][1] = r3;
            }
#pragma unroll
            for (int mt = 0; mt < 4; mt++)
#pragma unroll
                for (int nt = 0; nt < 4; nt++)
                    MMA16816H(acc[mt][nt], a[mt][0], a[mt][1], a[mt][2], a[mt][3],
                              bf[nt][0], bf[nt][1]);
        }

        if (s < 3) loadStoreA(s + 1);
        __syncthreads();                 // all MMA(s) reads + A(s+1) stores done
        if (s < 2) issueB(s + 2);        // safe: B buf (s&1) now free
        if (s < 3) {
            if (s < 2) CP_WAIT(1); else CP_WAIT(0);
            __syncthreads();
        }
    }

    // epilogue: sigmoid + fp16 STG (rows p, contiguous n)
    __half* outb = g_Wt + ((size_t)b * HW + p0) * NC + ny * 128;
#pragma unroll
    for (int mt = 0; mt < 4; mt++) {
        int pr = wm * 64 + mt * 16 + (lane >> 2);
#pragma unroll
        for (int nt = 0; nt < 4; nt++) {
            int nc = wn * 32 + nt * 8 + (lane & 3) * 2;
            float2 f0 = __half22float2(*(__half2*)&acc[mt][nt][0]);   // row pr
            float2 f1 = __half22float2(*(__half2*)&acc[mt][nt][1]);   // row pr+8
            *(__half2*)(outb + (size_t)pr * NC + nc) =
                __floats2half2_rn(1.f / (1.f + __expf(-f0.x)),
                                  1.f / (1.f + __expf(-f0.y)));
            *(__half2*)(outb + (size_t)(pr + 8) * NC + nc) =
                __floats2half2_rn(1.f / (1.f + __expf(-f1.x)),
                                  1.f / (1.f + __expf(-f1.y)));
        }
    }
}

// ---------------------------------------------------------------------------
// K2: selective warp-affine fill + softmax. 1 warp/pixel. fp16 in/out,
// half2 bilinear arithmetic. Writes CENTERED weights d = w - 1/256.
// ---------------------------------------------------------------------------
__global__ __launch_bounds__(256) void warp_softmax_kernel() {
    const int warp = threadIdx.x >> 5, lane = threadIdx.x & 31;
    const int g = blockIdx.x * 8 + warp;
    const int b = g / HW;
    const int p = g - b * HW;

    const __half* own = g_Wt + (size_t)g * NC;
    float v[8];
    {
        uint2 u0 = *(const uint2*)(own + lane * 4);
        uint2 u1 = *(const uint2*)(own + 128 + lane * 4);
        float2 f0 = __half22float2(*(__half2*)&u0.x), f1 = __half22float2(*(__half2*)&u0.y);
        float2 f2 = __half22float2(*(__half2*)&u1.x), f3 = __half22float2(*(__half2*)&u1.y);
        v[0] = f0.x; v[1] = f0.y; v[2] = f1.x; v[3] = f1.y;
        v[4] = f2.x; v[5] = f2.y; v[6] = f3.x; v[7] = f3.y;
    }

    if (b & 1) {   // agent > 0
        const int h = p / W_;
        const int w = p - h * W_;
        const float* th = g_theta[b];
        float gx = 2.f * (float)w / (float)(W_ - 1) - 1.f;
        float gy = 2.f * (float)h / (float)(H_ - 1) - 1.f;
        float cx2 = th[0] * gx + th[1] * gy + th[2];
        float cy2 = th[3] * gx + th[4] * gy + th[5];
        float x = (cx2 + 1.f) * (float)(W_ - 1) * 0.5f;
        float y = (cy2 + 1.f) * (float)(H_ - 1) * 0.5f;
        float x0f = floorf(x), y0f = floorf(y);
        int x0 = (int)x0f, y0 = (int)y0f;
        int x1 = x0 + 1,   y1 = y0 + 1;
        float fx = x - x0f, fy = y - y0f;
        bool vx0 = (x0 >= 0) && (x0 < W_), vx1 = (x1 >= 0) && (x1 < W_);
        bool vy0 = (y0 >= 0) && (y0 < H_), vy1 = (y1 >= 0) && (y1 < H_);
        float wa = (vx0 && vy0) ? (1.f - fx) * (1.f - fy) : 0.f;
        float wb = (vx1 && vy0) ? fx * (1.f - fy)         : 0.f;
        float wc = (vx0 && vy1) ? (1.f - fx) * fy         : 0.f;
        float wd = (vx1 && vy1) ? fx * fy                 : 0.f;
        int cx0 = min(max(x0, 0), W_ - 1), cx1 = min(max(x1, 0), W_ - 1);
        int cy0 = min(max(y0, 0), H_ - 1), cy1 = min(max(y1, 0), H_ - 1);

        const __half* ego = g_Wt + (size_t)(b - 1) * HW * NC;
        const __half* r00 = ego + (size_t)(cy0 * W_ + cx0) * NC;
        const __half* r10 = ego + (size_t)(cy0 * W_ + cx1) * NC;
        const __half* r01 = ego + (size_t)(cy1 * W_ + cx0) * NC;
        const __half* r11 = ego + (size_t)(cy1 * W_ + cx1) * NC;

        __half2 wah = __float2half2_rn(wa), wbh = __float2half2_rn(wb);
        __half2 wch = __float2half2_rn(wc), wdh = __float2half2_rn(wd);

        int4 m0 = *(const int4*)&g_masked[lane * 4];
        int4 m1 = *(const int4*)&g_masked[128 + lane * 4];
        int mk[8] = {m0.x, m0.y, m0.z, m0.w, m1.x, m1.y, m1.z, m1.w};

#pragma unroll
        for (int half = 0; half < 2; half++) {
            int off = half * 128 + lane * 4;
            uint2 ua = *(const uint2*)(r00 + off);
            uint2 uq = *(const uint2*)(r10 + off);
            uint2 uc = *(const uint2*)(r01 + off);
            uint2 ud = *(const uint2*)(r11 + off);
#pragma unroll
            for (int pr = 0; pr < 2; pr++) {
                __half2 av = *(__half2*)(pr ? &ua.y : &ua.x);
                __half2 qv = *(__half2*)(pr ? &uq.y : &uq.x);
                __half2 cv = *(__half2*)(pr ? &uc.y : &uc.x);
                __half2 dv = *(__half2*)(pr ? &ud.y : &ud.x);
                __half2 r = __hmul2(wah, av);
                r = __hfma2(wbh, qv, r);
                r = __hfma2(wch, cv, r);
                r = __hfma2(wdh, dv, r);
                float2 rf = __half22float2(r);
                int j0 = half * 4 + pr * 2;
                if (mk[j0])     v[j0]     = rf.x;
                if (mk[j0 + 1]) v[j0 + 1] = rf.y;
            }
        }
    }

    float m = v[0];
#pragma unroll
    for (int j = 1; j < 8; j++) m = fmaxf(m, v[j]);
#pragma unroll
    for (int o = 16; o > 0; o >>= 1) m = fmaxf(m, __shfl_xor_sync(0xffffffffu, m, o));
    float e[8]; float s = 0.f;
#pragma unroll
    for (int j = 0; j < 8; j++) { e[j] = __expf(v[j] - m); s += e[j]; }
#pragma unroll
    for (int o = 16; o > 0; o >>= 1) s += __shfl_xor_sync(0xffffffffu, s, o);
    float inv = 1.f / s;

    // write CENTERED tile-swizzled fp16 (GEMM2 A layout): d = w - 1/256
    const float MU = 1.0f / 256.0f;
    const int pl = p & 127;
    const size_t tb = (size_t)(b * NTILE + (p >> 7)) * 32768;
#pragma unroll
    for (int grp = 0; grp < 2; grp++) {
        int n0 = grp * 128 + lane * 4;
        int st = n0 >> 6, nl = n0 & 63;
        size_t eidx = tb + (size_t)st * 8192 + (size_t)(swz(pl, 2 * nl) >> 1);
        *(__half2*)(g_WsTh + eidx)     = __floats2half2_rn(e[grp * 4 + 0] * inv - MU,
                                                           e[grp * 4 + 1] * inv - MU);
        *(__half2*)(g_WsTh + eidx + 2) = __floats2half2_rn(e[grp * 4 + 2] * inv - MU,
                                                           e[grp * 4 + 3] * inv - MU);
    }
}

// ---------------------------------------------------------------------------
// GEMM2: out[c][p] = sum_n d[p][n]*cb[n][c] + colsum[c]   (fp16 accumulate)
// CTA: 128p x 128c; grid (2, 144, 8). 3 CTAs/SM.
// ---------------------------------------------------------------------------
__global__ __launch_bounds__(256, 3) void gemm2_mma(float* __restrict__ out) {
    extern __shared__ char smem_raw[];
    uint32_t sb0 = smem_u32(smem_raw);
    uint32_t base = (sb0 + 127u) & ~127u;
    char* smem = smem_raw + (base - sb0);

    const int tid = threadIdx.x;
    const int lane = tid & 31, warp = tid >> 5;
    const int wm = warp >> 2;
    const int wn = warp & 3;
    const int b  = blockIdx.z;
    const int cy = blockIdx.x;       // c block (fastest: L2 pairing)
    const int p0 = blockIdx.y * 128;

    const char* srcA = (const char*)(g_WsTh + (size_t)(b * NTILE + blockIdx.y) * 32768);
    const char* srcB = (const char*)(g_B2h + cy * 32768);

    auto issue = [&](int s) {
        uint32_t dA = base + (s & 1) * 32768;
        uint32_t dB = dA + 16384;
#pragma unroll
        for (int k = 0; k < 4; k++) {
            int idx = tid + k * 256;
            CP16(dA + idx * 16, srcA + (size_t)s * 16384 + idx * 16);
        }
#pragma unroll
        for (int k = 0; k < 4; k++) {
            int idx = tid + k * 256;
            CP16(dB + idx * 16, srcB + (size_t)s * 16384 + idx * 16);
        }
        CP_COMMIT();
    };

    issue(0);
    issue(1);

    int rA_off[4], xmA[4];
#pragma unroll
    for (int mt = 0; mt < 4; mt++) {
        int r = wm * 64 + mt * 16 + (lane & 15);
        rA_off[mt] = r * 128;
        xmA[mt] = (r & 7) << 4;
    }
    const int cb0A = (lane >> 4) << 4;
    int rB_off[2], xmB[2];
#pragma unroll
    for (int g = 0; g < 2; g++) {
        int r = wn * 32 + g * 16 + ((lane >> 4) << 3) + (lane & 7);
        rB_off[g] = r * 128;
        xmB[g] = (r & 7) << 4;
    }
    const int cb0B = ((lane >> 3) & 1) << 4;

    uint32_t acc[4][4][2];
#pragma unroll
    for (int i = 0; i < 4; i++)
#pragma unroll
        for (int j = 0; j < 4; j++) { acc[i][j][0] = 0u; acc[i][j][1] = 0u; }

    for (int s = 0; s < 4; s++) {
        if (s < 3) CP_WAIT(1); else CP_WAIT(0);
        __syncthreads();

        const uint32_t Abuf = base + (s & 1) * 32768;
        const uint32_t Bbuf = Abuf + 16384;
#pragma unroll
        for (int ks = 0; ks < 4; ks++) {
            uint32_t a[4][4], bf[4][2];
#pragma unroll
            for (int mt = 0; mt < 4; mt++)
                LDSM4(a[mt][0], a[mt][1], a[mt][2], a[mt][3],
                      Abuf + rA_off[mt] + ((ks * 32 + cb0A) ^ xmA[mt]));
#pragma unroll
            for (int g = 0; g < 2; g++) {
                uint32_t r0, r1, r2, r3;
                LDSM4(r0, r1, r2, r3, Bbuf + rB_off[g] + ((ks * 32 + cb0B) ^ xmB[g]));
                bf[2 * g][0] = r0; bf[2 * g][1] = r1;
                bf[2 * g + 1][0] = r2; bf[2 * g + 1][1] = r3;
            }
#pragma unroll
            for (int mt = 0; mt < 4; mt++)
#pragma unroll
                for (int nt = 0; nt < 4; nt++)
                    MMA16816H(acc[mt][nt], a[mt][0], a[mt][1], a[mt][2], a[mt][3],
                              bf[nt][0], bf[nt][1]);
        }
        __syncthreads();
        if (s < 2) issue(s + 2);
    }

    // epilogue: add colsum (mean term), transpose (p,c)->E[c][p], coalesced stores
    float* E = (float*)smem;
#pragma unroll
    for (int mt = 0; mt < 4; mt++) {
        int pr = wm * 64 + mt * 16 + (lane >> 2);
#pragma unroll
        for (int nt = 0; nt < 4; nt++) {
            int cc = wn * 32 + nt * 8 + (lane & 3) * 2;
            float cs0 = g_colsum[cy * 128 + cc];
            float cs1 = g_colsum[cy * 128 + cc + 1];
            float2 f0 = __half22float2(*(__half2*)&acc[mt][nt][0]);   // row pr
            float2 f1 = __half22float2(*(__half2*)&acc[mt][nt][1]);   // row pr+8
            E[cc * 132 + pr]           = f0.x + cs0;
            E[(cc + 1) * 132 + pr]     = f0.y + cs1;
            E[cc * 132 + pr + 8]       = f1.x + cs0;
            E[(cc + 1) * 132 + pr + 8] = f1.y + cs1;
        }
    }
    __syncthreads();

    float* ob = out + ((size_t)b * CD + cy * 128) * HW + p0;
#pragma unroll
    for (int i = 0; i < 16; i++) {
        int idx = tid + i * 256;           // 128 c-rows x 32 float4
        int c = idx >> 5, q = idx & 31;
        float4 v = *(float4*)&E[c * 132 + q * 4];
        *(float4*)(ob + (size_t)c * HW + q * 4) = v;
    }
}

// ---------------------------------------------------------------------------
extern "C" void kernel_launch(void* const* d_in, const int* in_sizes, int n_in,
                              void* d_out, int out_size) {
    (void)in_sizes; (void)n_in; (void)out_size;
    const float* feat = (const float*)d_in[0];
    const float* cb   = (const float*)d_in[1];
    const float* pub  = (const float*)d_in[2];
    const float* aff  = (const float*)d_in[3];
    float* out = (float*)d_out;

    cudaFuncSetAttribute(gemm1_mma, cudaFuncAttributeMaxDynamicSharedMemorySize, 65664);
    cudaFuncSetAttribute(gemm2_mma, cudaFuncAttributeMaxDynamicSharedMemorySize, 67712);

    setup_kernel<<<NC, 256>>>(cb, pub, aff);
    prep_kernel<<<NC, 256>>>(cb);

    gemm1_mma<<<dim3(2, NTILE, NB), 256, 65664>>>(feat);
    warp_softmax_kernel<<<NB * HW / 8, 256>>>();
    gemm2_mma<<<dim3(2, NTILE, NB), 256, 67712>>>(out);
}